// round 1
// baseline (speedup 1.0000x reference)
#include <cuda_runtime.h>

#define BATCH 4096
#define NCLS  10000
#define DIM   256
#define ALPHA 0.5f

// Scratch (allocation-free: __device__ globals)
__device__ float g_sumf[NCLS * DIM];  // sum of features per class
__device__ int   g_cnt[NCLS];         // per-class sample count

// ---------------------------------------------------------------------------
// Kernel 1: zero the scratch accumulators (graph-replay safe: re-zeroed each
// launch sequence).
// ---------------------------------------------------------------------------
__global__ void zero_scratch() {
    int i = blockIdx.x * blockDim.x + threadIdx.x;
    int n4 = NCLS * DIM / 4;  // 640000 float4s
    if (i < n4) {
        reinterpret_cast<float4*>(g_sumf)[i] = make_float4(0.f, 0.f, 0.f, 0.f);
    }
    if (i < NCLS) g_cnt[i] = 0;
}

// ---------------------------------------------------------------------------
// Kernel 2: one block (256 threads) per batch row.
//  a) scan onehot row (float4, strided) to find the single nonzero -> label.
//     Early exit via shared flag checked after each 4KB chunk: expected
//     ~55% of row read instead of 100%.
//  b) count the class, compute loss ||feat - centers[label]||^2 (block
//     reduction), scatter-add features into g_sumf[label].
// ---------------------------------------------------------------------------
__global__ __launch_bounds__(256, 8)
void row_kernel(const float* __restrict__ feat,
                const float* __restrict__ onehot,
                const float* __restrict__ centers,
                float* __restrict__ loss_out) {
    const int b = blockIdx.x;
    const int t = threadIdx.x;

    __shared__ int s_label;
    __shared__ float s_red[8];
    if (t == 0) s_label = -1;
    __syncthreads();

    // --- find label ---
    const float4* row = reinterpret_cast<const float4*>(onehot + (size_t)b * NCLS);
    const int NV4 = NCLS / 4;  // 2500
    int found = -1;
    #pragma unroll 1
    for (int it = 0; it < (NV4 + 255) / 256; ++it) {
        int i = it * 256 + t;
        if (i < NV4) {
            float4 v = row[i];
            if (v.x != 0.f)      found = 4 * i + 0;
            else if (v.y != 0.f) found = 4 * i + 1;
            else if (v.z != 0.f) found = 4 * i + 2;
            else if (v.w != 0.f) found = 4 * i + 3;
        }
        if (found >= 0) s_label = found;
        __syncthreads();
        if (s_label >= 0) break;
    }
    int label = s_label;
    if (label < 0) label = 0;  // defensive; cannot happen with true one-hot

    if (t == 0) atomicAdd(&g_cnt[label], 1);

    // --- loss + feature scatter (thread t handles dim t; D == blockDim) ---
    float f = feat[(size_t)b * DIM + t];
    float c = centers[(size_t)label * DIM + t];
    float d = f - c;
    float sq = d * d;

    // scatter features into per-class sum
    atomicAdd(&g_sumf[(size_t)label * DIM + t], f);

    // block reduction of sq
    #pragma unroll
    for (int off = 16; off > 0; off >>= 1)
        sq += __shfl_down_sync(0xFFFFFFFFu, sq, off);
    if ((t & 31) == 0) s_red[t >> 5] = sq;
    __syncthreads();
    if (t < 8) {
        float v = s_red[t];
        #pragma unroll
        for (int off = 4; off > 0; off >>= 1)
            v += __shfl_down_sync(0xFFu, v, off);
        if (t == 0) loss_out[b] = v;
    }
}

// ---------------------------------------------------------------------------
// Kernel 3: finalize new_centers = centers - ALPHA*(n_c*centers - sumf)/(n_c+1)
// ---------------------------------------------------------------------------
__global__ void finalize_kernel(const float* __restrict__ centers,
                                float* __restrict__ out_centers) {
    int i = blockIdx.x * blockDim.x + threadIdx.x;  // over C*D/4 float4s
    const int n4 = NCLS * DIM / 4;
    if (i >= n4) return;
    int c = i / (DIM / 4);  // 64 float4s per class row
    float cnt = (float)g_cnt[c];
    float scale = ALPHA / (cnt + 1.0f);
    float4 ce = reinterpret_cast<const float4*>(centers)[i];
    float4 sf = reinterpret_cast<const float4*>(g_sumf)[i];
    float4 o;
    o.x = ce.x - (cnt * ce.x - sf.x) * scale;
    o.y = ce.y - (cnt * ce.y - sf.y) * scale;
    o.z = ce.z - (cnt * ce.z - sf.z) * scale;
    o.w = ce.w - (cnt * ce.w - sf.w) * scale;
    reinterpret_cast<float4*>(out_centers)[i] = o;
}

// ---------------------------------------------------------------------------
extern "C" void kernel_launch(void* const* d_in, const int* in_sizes, int n_in,
                              void* d_out, int out_size) {
    const float* feat    = (const float*)d_in[0];  // [4096, 256]
    const float* onehot  = (const float*)d_in[1];  // [4096, 10000]
    const float* centers = (const float*)d_in[2];  // [10000, 256]

    float* loss_out    = (float*)d_out;            // [4096]
    float* centers_out = (float*)d_out + BATCH;    // [10000, 256]

    // 1) zero scratch: 640000 float4s -> 2500 blocks x 256
    zero_scratch<<<2500, 256>>>();
    // 2) per-row work
    row_kernel<<<BATCH, 256>>>(feat, onehot, centers, loss_out);
    // 3) finalize centers: 640000 float4s
    finalize_kernel<<<2500, 256>>>(centers, centers_out);
}

// round 2
// speedup vs baseline: 1.0408x; 1.0408x over previous
#include <cuda_runtime.h>

#define BATCH 4096
#define NCLS  10000
#define DIM   256
#define ALPHA 0.5f

// Scratch (allocation-free: __device__ globals)
__device__ int g_cnt[NCLS];     // per-class sample count
__device__ int g_label[BATCH];  // decoded label per row

// ---------------------------------------------------------------------------
// K1: zero the per-class counters (40 KB only).
// ---------------------------------------------------------------------------
__global__ void zero_cnt() {
    int i = blockIdx.x * blockDim.x + threadIdx.x;
    if (i < NCLS) g_cnt[i] = 0;
}

// ---------------------------------------------------------------------------
// K2: one block (256 threads) per batch row. Early-exit forward scan of the
// onehot row in 4 KB chunks; the single finder thread records the label and
// bumps the class count. Expected read ~55% of the row.
// ---------------------------------------------------------------------------
__global__ __launch_bounds__(256, 8)
void scan_kernel(const float* __restrict__ onehot) {
    const int b = blockIdx.x;
    const int t = threadIdx.x;

    __shared__ int s_label;
    if (t == 0) s_label = -1;
    __syncthreads();

    const float4* row = reinterpret_cast<const float4*>(onehot + (size_t)b * NCLS);
    const int NV4 = NCLS / 4;  // 2500

    #pragma unroll 1
    for (int it = 0; it < (NV4 + 255) / 256; ++it) {
        int i = it * 256 + t;
        if (i < NV4) {
            float4 v = row[i];
            int found = -1;
            if (v.x != 0.f)      found = 4 * i + 0;
            else if (v.y != 0.f) found = 4 * i + 1;
            else if (v.z != 0.f) found = 4 * i + 2;
            else if (v.w != 0.f) found = 4 * i + 3;
            if (found >= 0) {
                s_label = found;
                g_label[b] = found;
                atomicAdd(&g_cnt[found], 1);
            }
        }
        __syncthreads();
        if (s_label >= 0) break;
    }
}

// ---------------------------------------------------------------------------
// K3: out_centers = centers * (1 - ALPHA*n/(n+1))   (the linear part).
// ---------------------------------------------------------------------------
__global__ __launch_bounds__(256)
void scale_kernel(const float* __restrict__ centers,
                  float* __restrict__ out_centers) {
    int i = blockIdx.x * blockDim.x + threadIdx.x;  // over C*D/4 float4s
    const int n4 = NCLS * DIM / 4;
    if (i >= n4) return;
    int c = i >> 6;  // 64 float4s per class row
    float n = (float)g_cnt[c];
    float k = 1.0f - ALPHA * n / (n + 1.0f);
    float4 ce = reinterpret_cast<const float4*>(centers)[i];
    float4 o;
    o.x = ce.x * k;
    o.y = ce.y * k;
    o.z = ce.z * k;
    o.w = ce.w * k;
    reinterpret_cast<float4*>(out_centers)[i] = o;
}

// ---------------------------------------------------------------------------
// K4: per-row loss (vs OLD centers) + scatter ALPHA*f/(n+1) into out_centers.
// ---------------------------------------------------------------------------
__global__ __launch_bounds__(256, 8)
void loss_scatter_kernel(const float* __restrict__ feat,
                         const float* __restrict__ centers,
                         float* __restrict__ loss_out,
                         float* __restrict__ out_centers) {
    const int b = blockIdx.x;
    const int t = threadIdx.x;
    __shared__ float s_red[8];

    const int label = g_label[b];
    const float n = (float)g_cnt[label];
    const float s = ALPHA / (n + 1.0f);

    float f = feat[(size_t)b * DIM + t];
    float c = centers[(size_t)label * DIM + t];
    float d = f - c;
    float sq = d * d;

    // scatter linear contribution into output centers
    atomicAdd(&out_centers[(size_t)label * DIM + t], s * f);

    // block reduction of sq -> loss
    #pragma unroll
    for (int off = 16; off > 0; off >>= 1)
        sq += __shfl_down_sync(0xFFFFFFFFu, sq, off);
    if ((t & 31) == 0) s_red[t >> 5] = sq;
    __syncthreads();
    if (t < 8) {
        float v = s_red[t];
        #pragma unroll
        for (int off = 4; off > 0; off >>= 1)
            v += __shfl_down_sync(0xFFu, v, off);
        if (t == 0) loss_out[b] = v;
    }
}

// ---------------------------------------------------------------------------
extern "C" void kernel_launch(void* const* d_in, const int* in_sizes, int n_in,
                              void* d_out, int out_size) {
    const float* feat    = (const float*)d_in[0];  // [4096, 256]
    const float* onehot  = (const float*)d_in[1];  // [4096, 10000]
    const float* centers = (const float*)d_in[2];  // [10000, 256]

    float* loss_out    = (float*)d_out;            // [4096]
    float* centers_out = (float*)d_out + BATCH;    // [10000, 256]

    zero_cnt<<<(NCLS + 255) / 256, 256>>>();
    scan_kernel<<<BATCH, 256>>>(onehot);
    scale_kernel<<<(NCLS * DIM / 4 + 255) / 256, 256>>>(centers, centers_out);
    loss_scatter_kernel<<<BATCH, 256>>>(feat, centers, loss_out, centers_out);
}

// round 3
// speedup vs baseline: 1.1026x; 1.0594x over previous
#include <cuda_runtime.h>

#define BATCH 4096
#define NCLS  10000
#define DIM   256
#define ALPHA 0.5f
#define CAP   64   // per-class row-list capacity (overflow handled exactly)

// Scratch (allocation-free: __device__ globals)
__device__ int g_cnt[NCLS];         // per-class sample count
__device__ int g_label[BATCH];      // decoded label per row (overflow fallback)
__device__ int g_rows[NCLS * CAP];  // per-class row index list

// ---------------------------------------------------------------------------
// K1: zero the per-class counters (40 KB).
// ---------------------------------------------------------------------------
__global__ void zero_cnt() {
    int i = blockIdx.x * blockDim.x + threadIdx.x;
    if (i < NCLS) g_cnt[i] = 0;
}

// ---------------------------------------------------------------------------
// K2: one block per batch row.
//  a) early-exit scan of the onehot row (float4, 4KB chunks) -> label
//  b) finder thread: bump count, append row to class list
//  c) ALL threads: loss ||feat - centers[label]||^2 (gather hidden under the
//     BW-bound scan of other blocks)
// ---------------------------------------------------------------------------
__global__ __launch_bounds__(256, 8)
void scan_loss_kernel(const float* __restrict__ onehot,
                      const float* __restrict__ feat,
                      const float* __restrict__ centers,
                      float* __restrict__ loss_out) {
    const int b = blockIdx.x;
    const int t = threadIdx.x;

    __shared__ int s_label;
    __shared__ float s_red[8];
    if (t == 0) s_label = -1;
    __syncthreads();

    const float4* row = reinterpret_cast<const float4*>(onehot + (size_t)b * NCLS);
    const int NV4 = NCLS / 4;  // 2500

    #pragma unroll 1
    for (int it = 0; it < (NV4 + 255) / 256; ++it) {
        int i = it * 256 + t;
        if (i < NV4) {
            float4 v = row[i];
            int found = -1;
            if (v.x != 0.f)      found = 4 * i + 0;
            else if (v.y != 0.f) found = 4 * i + 1;
            else if (v.z != 0.f) found = 4 * i + 2;
            else if (v.w != 0.f) found = 4 * i + 3;
            if (found >= 0) {
                s_label = found;
                g_label[b] = found;
                int slot = atomicAdd(&g_cnt[found], 1);
                if (slot < CAP) g_rows[found * CAP + slot] = b;
            }
        }
        __syncthreads();
        if (s_label >= 0) break;
    }

    const int label = s_label;

    // loss vs OLD centers
    float f = feat[(size_t)b * DIM + t];
    float c = centers[(size_t)label * DIM + t];
    float d = f - c;
    float sq = d * d;
    #pragma unroll
    for (int off = 16; off > 0; off >>= 1)
        sq += __shfl_down_sync(0xFFFFFFFFu, sq, off);
    if ((t & 31) == 0) s_red[t >> 5] = sq;
    __syncthreads();
    if (t < 8) {
        float v = s_red[t];
        #pragma unroll
        for (int off = 4; off > 0; off >>= 1)
            v += __shfl_down_sync(0xFFu, v, off);
        if (t == 0) loss_out[b] = v;
    }
}

// ---------------------------------------------------------------------------
// K3: one warp per class. out_c = k*centers_c + s * sum(feat rows of class c)
//     k = 1 - ALPHA*n/(n+1), s = ALPHA/(n+1). Atomic-free, single write.
// ---------------------------------------------------------------------------
__global__ __launch_bounds__(256)
void scale_gather_kernel(const float* __restrict__ centers,
                         const float* __restrict__ feat,
                         float* __restrict__ out_centers) {
    const int warp = (blockIdx.x * blockDim.x + threadIdx.x) >> 5;
    if (warp >= NCLS) return;
    const int lane = threadIdx.x & 31;

    const int n = g_cnt[warp];
    const float fn = (float)n;
    const float k = 1.0f - ALPHA * fn / (fn + 1.0f);
    const float s = ALPHA / (fn + 1.0f);

    const float4* crow = reinterpret_cast<const float4*>(centers + (size_t)warp * DIM);
    float4 a0 = crow[lane];
    float4 a1 = crow[lane + 32];
    a0.x *= k; a0.y *= k; a0.z *= k; a0.w *= k;
    a1.x *= k; a1.y *= k; a1.z *= k; a1.w *= k;

    if (n > 0) {
        if (n <= CAP) {
            #pragma unroll 1
            for (int j = 0; j < n; ++j) {
                int b = g_rows[warp * CAP + j];
                const float4* fr = reinterpret_cast<const float4*>(feat + (size_t)b * DIM);
                float4 f0 = fr[lane];
                float4 f1 = fr[lane + 32];
                a0.x += s * f0.x; a0.y += s * f0.y; a0.z += s * f0.z; a0.w += s * f0.w;
                a1.x += s * f1.x; a1.y += s * f1.y; a1.z += s * f1.z; a1.w += s * f1.w;
            }
        } else {
            // exhaustive fallback (statistically unreachable; exact correctness)
            #pragma unroll 1
            for (int b = 0; b < BATCH; ++b) {
                if (g_label[b] == warp) {
                    const float4* fr = reinterpret_cast<const float4*>(feat + (size_t)b * DIM);
                    float4 f0 = fr[lane];
                    float4 f1 = fr[lane + 32];
                    a0.x += s * f0.x; a0.y += s * f0.y; a0.z += s * f0.z; a0.w += s * f0.w;
                    a1.x += s * f1.x; a1.y += s * f1.y; a1.z += s * f1.z; a1.w += s * f1.w;
                }
            }
        }
    }

    float4* orow = reinterpret_cast<float4*>(out_centers + (size_t)warp * DIM);
    orow[lane]      = a0;
    orow[lane + 32] = a1;
}

// ---------------------------------------------------------------------------
extern "C" void kernel_launch(void* const* d_in, const int* in_sizes, int n_in,
                              void* d_out, int out_size) {
    const float* feat    = (const float*)d_in[0];  // [4096, 256]
    const float* onehot  = (const float*)d_in[1];  // [4096, 10000]
    const float* centers = (const float*)d_in[2];  // [10000, 256]

    float* loss_out    = (float*)d_out;            // [4096]
    float* centers_out = (float*)d_out + BATCH;    // [10000, 256]

    zero_cnt<<<(NCLS + 255) / 256, 256>>>();
    scan_loss_kernel<<<BATCH, 256>>>(onehot, feat, centers, loss_out);
    // 10000 classes, one warp each -> 10000*32 threads / 256 = 1250 blocks
    scale_gather_kernel<<<(NCLS * 32 + 255) / 256, 256>>>(centers, feat, centers_out);
}